// round 12
// baseline (speedup 1.0000x reference)
#include <cuda_runtime.h>
#include <cuda_bf16.h>

#define N_NODES 100000
#define N_EDGES 1600000
#define FEATS   128
#define EPW     4          // edges per warp in scatter

typedef unsigned long long u64;

// Scratch (static device arrays — no runtime allocation).
__device__ float g_agg[N_NODES * FEATS];   // 51.2 MB
__device__ int   g_deg_s[N_NODES];
__device__ int   g_deg_d[N_NODES];
__device__ float g_rs_s[N_NODES];          // clip(deg_out,1)^{-1/2}
__device__ float g_rs_d[N_NODES];          // clip(deg_in, 1)^{-1/2}

// Packed dual-fp32 FMA (sm_103a FFMA2; ptxas never auto-fuses this).
__device__ __forceinline__ u64 fma_f32x2(u64 a, u64 b, u64 c) {
    u64 d;
    asm("fma.rn.f32x2 %0, %1, %2, %3;" : "=l"(d) : "l"(a), "l"(b), "l"(c));
    return d;
}
__device__ __forceinline__ u64 splat_f32x2(float a) {
    u64 d;
    unsigned int ai = __float_as_uint(a);
    asm("mov.b64 %0, {%1, %1};" : "=l"(d) : "r"(ai));
    return d;
}
__device__ __forceinline__ void unpack_f32x2(u64 p, float& lo, float& hi) {
    asm("mov.b64 {%0, %1}, %2;" : "=f"(lo), "=f"(hi) : "l"(p));
}

// ---------------------------------------------------------------------------
// Kernel 1: degree counting. 4 edges per thread via int4 loads.
// ---------------------------------------------------------------------------
__global__ void degree_kernel(const int* __restrict__ src,
                              const int* __restrict__ dst) {
    int i = blockIdx.x * blockDim.x + threadIdx.x;
    const int n4 = N_EDGES / 4;
    if (i < n4) {
        int4 s4 = ((const int4*)src)[i];
        int4 d4 = ((const int4*)dst)[i];
        atomicAdd(&g_deg_s[s4.x], 1);
        atomicAdd(&g_deg_s[s4.y], 1);
        atomicAdd(&g_deg_s[s4.z], 1);
        atomicAdd(&g_deg_s[s4.w], 1);
        atomicAdd(&g_deg_d[d4.x], 1);
        atomicAdd(&g_deg_d[d4.y], 1);
        atomicAdd(&g_deg_d[d4.z], 1);
        atomicAdd(&g_deg_d[d4.w], 1);
    }
}

// ---------------------------------------------------------------------------
// Kernel 2: rs = clip(deg,1)^{-1/2} as float, once per node.
// ---------------------------------------------------------------------------
__global__ void rsqrt_kernel() {
    int i = blockIdx.x * blockDim.x + threadIdx.x;
    if (i < N_NODES) {
        int ds = g_deg_s[i]; if (ds < 1) ds = 1;
        int dd = g_deg_d[i]; if (dd < 1) dd = 1;
        g_rs_s[i] = rsqrtf((float)ds);
        g_rs_d[i] = rsqrtf((float)dd);
    }
}

// ---------------------------------------------------------------------------
// Kernel 3: fused src-normalize + gather + scatter-add.
// Each warp processes EPW consecutive edges (MLP~4 on the gather path);
// lane l handles the l-th 16B chunk of the 512B feature row.
// red.relaxed.gpu.global.add.v4.f32 -> one 16B L2 reduction per lane.
// ---------------------------------------------------------------------------
__global__ void __launch_bounds__(256)
scatter_kernel(const float* __restrict__ feat,
               const int* __restrict__ src,
               const int* __restrict__ dst) {
    const int warp = threadIdx.x >> 5;
    const int lane = threadIdx.x & 31;
    const int e0 = (blockIdx.x * 8 + warp) * EPW;

    if (e0 + EPW <= N_EDGES) {
        int s[EPW], d[EPW];
        float sc[EPW];
#pragma unroll
        for (int i = 0; i < EPW; ++i) {
            s[i] = __ldg(src + e0 + i);
            d[i] = __ldg(dst + e0 + i);
        }
#pragma unroll
        for (int i = 0; i < EPW; ++i) sc[i] = g_rs_s[s[i]];

        float4 v[EPW];
#pragma unroll
        for (int i = 0; i < EPW; ++i)
            v[i] = *reinterpret_cast<const float4*>(feat + (size_t)s[i] * FEATS + lane * 4);

#pragma unroll
        for (int i = 0; i < EPW; ++i) {
            float4 w;
            w.x = v[i].x * sc[i]; w.y = v[i].y * sc[i];
            w.z = v[i].z * sc[i]; w.w = v[i].w * sc[i];
            float* p = g_agg + (size_t)d[i] * FEATS + lane * 4;
            asm volatile("red.relaxed.gpu.global.add.v4.f32 [%0], {%1, %2, %3, %4};"
                         :: "l"(p), "f"(w.x), "f"(w.y), "f"(w.z), "f"(w.w)
                         : "memory");
        }
    } else {
        for (int e = e0; e < N_EDGES; ++e) {
            const int s = __ldg(src + e);
            const int d = __ldg(dst + e);
            const float sc = g_rs_s[s];
            const float4 v = *reinterpret_cast<const float4*>(feat + (size_t)s * FEATS + lane * 4);
            float4 w;
            w.x = v.x * sc; w.y = v.y * sc; w.z = v.z * sc; w.w = v.w * sc;
            float* p = g_agg + (size_t)d * FEATS + lane * 4;
            asm volatile("red.relaxed.gpu.global.add.v4.f32 [%0], {%1, %2, %3, %4};"
                         :: "l"(p), "f"(w.x), "f"(w.y), "f"(w.z), "f"(w.w)
                         : "memory");
        }
    }
}

// ---------------------------------------------------------------------------
// Kernel 4: out = relu( (rs_in ⊙ agg) @ W + bias )
// Block tile: 64 rows x 128 cols. 256 threads; each thread: 8 rows x 4 cols.
// Quad-k inner loop: A via one LDS.128 per (row, k-quad) (warp-broadcast),
// B via one LDS.128 per (k, col-quad). Shared accesses cut ~3.3x vs scalar.
// Math via packed fma.rn.f32x2 (FFMA2).
// ---------------------------------------------------------------------------
__global__ void __launch_bounds__(256)
gemm_kernel(const float* __restrict__ W,      // [128,128] row-major (k, h)
            const float* __restrict__ bias,   // [128]
            float* __restrict__ out) {        // [N,128]
    __shared__ float sA[64][32];   // agg tile [row][k] (pre-scaled by rs_in)
    __shared__ float sB[32][128];  // W chunk  [k][col]
    __shared__ float sScale[64];   // rs_in per tile row

    const int tid = threadIdx.x;
    const int tx = tid & 31;       // col group: cols 4*tx .. 4*tx+3
    const int ty = tid >> 5;       // row group: rows ty*8 .. ty*8+7
    const int base = blockIdx.x * 64;

    if (tid < 64) {
        int g = base + tid;
        if (g > N_NODES - 1) g = N_NODES - 1;
        sScale[tid] = g_rs_d[g];
    }
    __syncthreads();

    u64 acc2[8][2];   // 8 rows x 2 packed f32x2 (cols 0-1, 2-3)
#pragma unroll
    for (int r = 0; r < 8; ++r) { acc2[r][0] = 0ull; acc2[r][1] = 0ull; }

    for (int kc = 0; kc < 4; ++kc) {
        // Load agg tile: 64 rows x 32 k = 512 float4, scaled by rs_in[row]
#pragma unroll
        for (int it = 0; it < 2; ++it) {
            int f = tid + it * 256;          // 0..511
            int row = f >> 3;
            int k4 = f & 7;
            int g = base + row;
            if (g > N_NODES - 1) g = N_NODES - 1;   // clamp (stores guarded)
            float4 v = *reinterpret_cast<const float4*>(
                g_agg + (size_t)g * FEATS + kc * 32 + k4 * 4);
            float sc = sScale[row];
            v.x *= sc; v.y *= sc; v.z *= sc; v.w *= sc;
            *reinterpret_cast<float4*>(&sA[row][k4 * 4]) = v;
        }
        // Load W chunk: 32 k x 128 cols = 1024 float4
#pragma unroll
        for (int it = 0; it < 4; ++it) {
            int f = tid + it * 256;          // 0..1023
            int k = f >> 5;
            int c4 = f & 31;
            float4 v = *reinterpret_cast<const float4*>(
                W + (size_t)(kc * 32 + k) * FEATS + c4 * 4);
            *reinterpret_cast<float4*>(&sB[k][c4 * 4]) = v;
        }
        __syncthreads();

#pragma unroll
        for (int kq = 0; kq < 8; ++kq) {      // 8 quads of k
            // B quad: 4 consecutive k rows, one LDS.128 each.
            u64 b01[4], b23[4];
#pragma unroll
            for (int j = 0; j < 4; ++j) {
                const u64* bp = reinterpret_cast<const u64*>(&sB[kq * 4 + j][tx * 4]);
                b01[j] = bp[0];
                b23[j] = bp[1];
            }
#pragma unroll
            for (int r = 0; r < 8; ++r) {
                // A quad: one broadcast LDS.128 (all lanes same address).
                float4 a = *reinterpret_cast<const float4*>(&sA[ty * 8 + r][kq * 4]);
                acc2[r][0] = fma_f32x2(splat_f32x2(a.x), b01[0], acc2[r][0]);
                acc2[r][1] = fma_f32x2(splat_f32x2(a.x), b23[0], acc2[r][1]);
                acc2[r][0] = fma_f32x2(splat_f32x2(a.y), b01[1], acc2[r][0]);
                acc2[r][1] = fma_f32x2(splat_f32x2(a.y), b23[1], acc2[r][1]);
                acc2[r][0] = fma_f32x2(splat_f32x2(a.z), b01[2], acc2[r][0]);
                acc2[r][1] = fma_f32x2(splat_f32x2(a.z), b23[2], acc2[r][1]);
                acc2[r][0] = fma_f32x2(splat_f32x2(a.w), b01[3], acc2[r][0]);
                acc2[r][1] = fma_f32x2(splat_f32x2(a.w), b23[3], acc2[r][1]);
            }
        }
        __syncthreads();
    }

    // Epilogue: + bias, relu, store
    float4 bb = *reinterpret_cast<const float4*>(bias + tx * 4);
#pragma unroll
    for (int r = 0; r < 8; ++r) {
        int g = base + ty * 8 + r;
        if (g < N_NODES) {
            float a0, a1, a2, a3;
            unpack_f32x2(acc2[r][0], a0, a1);
            unpack_f32x2(acc2[r][1], a2, a3);
            float4 o;
            o.x = fmaxf(a0 + bb.x, 0.f);
            o.y = fmaxf(a1 + bb.y, 0.f);
            o.z = fmaxf(a2 + bb.z, 0.f);
            o.w = fmaxf(a3 + bb.w, 0.f);
            *reinterpret_cast<float4*>(out + (size_t)g * FEATS + tx * 4) = o;
        }
    }
}

// ---------------------------------------------------------------------------
extern "C" void kernel_launch(void* const* d_in, const int* in_sizes, int n_in,
                              void* d_out, int out_size) {
    const float* features = (const float*)d_in[0];
    const int*   src      = (const int*)d_in[1];
    const int*   dst      = (const int*)d_in[2];
    const float* weight   = (const float*)d_in[3];
    const float* bias     = (const float*)d_in[4];
    float* out = (float*)d_out;

    // Resolve scratch symbol addresses once (deterministic, capture-safe).
    static void* p_agg = nullptr;
    static void* p_ds  = nullptr;
    static void* p_dd  = nullptr;
    if (!p_agg) {
        cudaGetSymbolAddress(&p_agg, g_agg);
        cudaGetSymbolAddress(&p_ds,  g_deg_s);
        cudaGetSymbolAddress(&p_dd,  g_deg_d);
    }

    // 1) zero scratch via the copy engine (capture-legal, no SM time).
    cudaMemsetAsync(p_agg, 0, sizeof(float) * N_NODES * FEATS);
    cudaMemsetAsync(p_ds,  0, sizeof(int) * N_NODES);
    cudaMemsetAsync(p_dd,  0, sizeof(int) * N_NODES);

    // 2) degrees (4 edges per thread)
    degree_kernel<<<((N_EDGES / 4) + 255) / 256, 256>>>(src, dst);
    // 2b) per-node D^{-1/2}
    rsqrt_kernel<<<(N_NODES + 255) / 256, 256>>>();
    // 3) src-normalize + gather + scatter (8 warps x EPW edges per block)
    {
        int edges_per_block = 8 * EPW;   // 32
        scatter_kernel<<<(N_EDGES + edges_per_block - 1) / edges_per_block, 256>>>(
            features, src, dst);
    }
    // 4) GEMM (quad-k FFMA2) + rs_in scale + bias + relu
    gemm_kernel<<<(N_NODES + 63) / 64, 256>>>(weight, bias, out);
}

// round 17
// speedup vs baseline: 1.2792x; 1.2792x over previous
#include <cuda_runtime.h>
#include <cuda_bf16.h>

#define N_NODES 100000
#define N_EDGES 1600000
#define FEATS   128
#define NBLK    98          // ceil(N_NODES / 1024) scan blocks

typedef unsigned long long u64;

// Scratch (static device arrays — no runtime allocation).
__device__ float g_agg[N_NODES * FEATS];   // 51.2 MB (fully overwritten)
__device__ int   g_deg[2 * N_NODES];       // [0:N) = deg_src, [N:2N) = deg_dst
__device__ float g_rs_s[N_NODES];          // clip(deg_out,1)^{-1/2}
__device__ float g_rs_d[N_NODES];          // clip(deg_in, 1)^{-1/2}
__device__ int   g_off[N_NODES];           // CSR row offsets (exclusive scan of deg_dst)
__device__ int   g_cur[N_NODES];           // binning cursors (init = g_off)
__device__ int   g_csr[N_EDGES];           // src ids grouped by dst
__device__ int   g_bsum[NBLK];             // scan block sums
__device__ int   g_bbase[NBLK];            // scanned block bases

// Packed dual-fp32 FMA (sm_103a FFMA2).
__device__ __forceinline__ u64 fma_f32x2(u64 a, u64 b, u64 c) {
    u64 d;
    asm("fma.rn.f32x2 %0, %1, %2, %3;" : "=l"(d) : "l"(a), "l"(b), "l"(c));
    return d;
}
__device__ __forceinline__ u64 splat_f32x2(float a) {
    u64 d;
    unsigned int ai = __float_as_uint(a);
    asm("mov.b64 %0, {%1, %1};" : "=l"(d) : "r"(ai));
    return d;
}
__device__ __forceinline__ void unpack_f32x2(u64 p, float& lo, float& hi) {
    asm("mov.b64 {%0, %1}, %2;" : "=f"(lo), "=f"(hi) : "l"(p));
}

// ---------------------------------------------------------------------------
// Degrees: 4 edges per thread via int4 loads.
// ---------------------------------------------------------------------------
__global__ void degree_kernel(const int* __restrict__ src,
                              const int* __restrict__ dst) {
    int i = blockIdx.x * blockDim.x + threadIdx.x;
    const int n4 = N_EDGES / 4;
    if (i < n4) {
        int4 s4 = ((const int4*)src)[i];
        int4 d4 = ((const int4*)dst)[i];
        atomicAdd(&g_deg[s4.x], 1);
        atomicAdd(&g_deg[s4.y], 1);
        atomicAdd(&g_deg[s4.z], 1);
        atomicAdd(&g_deg[s4.w], 1);
        atomicAdd(&g_deg[N_NODES + d4.x], 1);
        atomicAdd(&g_deg[N_NODES + d4.y], 1);
        atomicAdd(&g_deg[N_NODES + d4.z], 1);
        atomicAdd(&g_deg[N_NODES + d4.w], 1);
    }
}

// ---------------------------------------------------------------------------
// Scan stage 1: per-1024-block exclusive scan of deg_dst -> g_off, totals -> g_bsum.
// ---------------------------------------------------------------------------
__global__ void __launch_bounds__(1024) scan1_kernel() {
    __shared__ int sh[1024];
    int t = threadIdx.x;
    int gid = blockIdx.x * 1024 + t;
    int val = (gid < N_NODES) ? g_deg[N_NODES + gid] : 0;
    sh[t] = val;
    __syncthreads();
#pragma unroll
    for (int ofs = 1; ofs < 1024; ofs <<= 1) {
        int add = (t >= ofs) ? sh[t - ofs] : 0;
        __syncthreads();
        sh[t] += add;
        __syncthreads();
    }
    if (gid < N_NODES) g_off[gid] = sh[t] - val;    // exclusive
    if (t == 1023) g_bsum[blockIdx.x] = sh[1023];
}

// ---------------------------------------------------------------------------
// Scan stage 2: exclusive scan of NBLK block sums (one block).
// ---------------------------------------------------------------------------
__global__ void __launch_bounds__(128) scan2_kernel() {
    __shared__ int sh[128];
    int t = threadIdx.x;
    int val = (t < NBLK) ? g_bsum[t] : 0;
    sh[t] = val;
    __syncthreads();
#pragma unroll
    for (int ofs = 1; ofs < 128; ofs <<= 1) {
        int add = (t >= ofs) ? sh[t - ofs] : 0;
        __syncthreads();
        sh[t] += add;
        __syncthreads();
    }
    if (t < NBLK) g_bbase[t] = sh[t] - val;         // exclusive
}

// ---------------------------------------------------------------------------
// Scan stage 3 (fused): fold block bases into per-node offsets AND compute
// the per-node D^{-1/2} scales (one pass over node range instead of two).
// ---------------------------------------------------------------------------
__global__ void scan3_rsqrt_kernel() {
    int i = blockIdx.x * blockDim.x + threadIdx.x;
    if (i < N_NODES) {
        g_off[i] += g_bbase[i >> 10];
        int ds = g_deg[i];            if (ds < 1) ds = 1;
        int dd = g_deg[N_NODES + i];  if (dd < 1) dd = 1;
        g_rs_s[i] = rsqrtf((float)ds);
        g_rs_d[i] = rsqrtf((float)dd);
    }
}

// ---------------------------------------------------------------------------
// Binning: scatter src ids into dst-grouped CSR. 4 edges per thread.
// g_cur is pre-initialized to g_off (D2D copy), so the atomic's return value
// IS the absolute CSR slot — no extra offset load per edge.
// ---------------------------------------------------------------------------
__global__ void bin_kernel(const int* __restrict__ src,
                           const int* __restrict__ dst) {
    int i = blockIdx.x * blockDim.x + threadIdx.x;
    const int n4 = N_EDGES / 4;
    if (i < n4) {
        int4 s4 = ((const int4*)src)[i];
        int4 d4 = ((const int4*)dst)[i];
        g_csr[atomicAdd(&g_cur[d4.x], 1)] = s4.x;
        g_csr[atomicAdd(&g_cur[d4.y], 1)] = s4.y;
        g_csr[atomicAdd(&g_cur[d4.z], 1)] = s4.z;
        g_csr[atomicAdd(&g_cur[d4.w], 1)] = s4.w;
    }
}

// ---------------------------------------------------------------------------
// Aggregate: one warp per dst node. Lane l owns the l-th 16B chunk of the
// 512B feature row; neighbors accumulated in registers, one store per row.
// 2-way unrolled edge loop (dual accumulators -> gather MLP~2).
// agg[n] = sum_{s in in(n)} rs_s[s] * feat[s]   (rs_d applied in GEMM).
// ---------------------------------------------------------------------------
__global__ void __launch_bounds__(256)
aggregate_kernel(const float* __restrict__ feat) {
    const int warp = (blockIdx.x * blockDim.x + threadIdx.x) >> 5;
    const int lane = threadIdx.x & 31;
    if (warp >= N_NODES) return;

    const int beg = g_off[warp];
    const int cnt = g_deg[N_NODES + warp];

    float4 acc0 = make_float4(0.f, 0.f, 0.f, 0.f);
    float4 acc1 = make_float4(0.f, 0.f, 0.f, 0.f);

    int j = 0;
    for (; j + 1 < cnt; j += 2) {
        const int s0 = __ldg(g_csr + beg + j);
        const int s1 = __ldg(g_csr + beg + j + 1);
        const float sc0 = g_rs_s[s0];
        const float sc1 = g_rs_s[s1];
        const float4 v0 = *reinterpret_cast<const float4*>(
            feat + (size_t)s0 * FEATS + lane * 4);
        const float4 v1 = *reinterpret_cast<const float4*>(
            feat + (size_t)s1 * FEATS + lane * 4);
        acc0.x = fmaf(v0.x, sc0, acc0.x);
        acc0.y = fmaf(v0.y, sc0, acc0.y);
        acc0.z = fmaf(v0.z, sc0, acc0.z);
        acc0.w = fmaf(v0.w, sc0, acc0.w);
        acc1.x = fmaf(v1.x, sc1, acc1.x);
        acc1.y = fmaf(v1.y, sc1, acc1.y);
        acc1.z = fmaf(v1.z, sc1, acc1.z);
        acc1.w = fmaf(v1.w, sc1, acc1.w);
    }
    if (j < cnt) {
        const int s0 = __ldg(g_csr + beg + j);
        const float sc0 = g_rs_s[s0];
        const float4 v0 = *reinterpret_cast<const float4*>(
            feat + (size_t)s0 * FEATS + lane * 4);
        acc0.x = fmaf(v0.x, sc0, acc0.x);
        acc0.y = fmaf(v0.y, sc0, acc0.y);
        acc0.z = fmaf(v0.z, sc0, acc0.z);
        acc0.w = fmaf(v0.w, sc0, acc0.w);
    }
    acc0.x += acc1.x; acc0.y += acc1.y; acc0.z += acc1.z; acc0.w += acc1.w;

    *reinterpret_cast<float4*>(g_agg + (size_t)warp * FEATS + lane * 4) = acc0;
}

// ---------------------------------------------------------------------------
// GEMM: out = relu( (rs_in ⊙ agg) @ W + bias ). 64x128 tile, FFMA2 quad-k.
// ---------------------------------------------------------------------------
__global__ void __launch_bounds__(256)
gemm_kernel(const float* __restrict__ W,      // [128,128] row-major (k, h)
            const float* __restrict__ bias,   // [128]
            float* __restrict__ out) {        // [N,128]
    __shared__ float sA[64][32];
    __shared__ float sB[32][128];
    __shared__ float sScale[64];

    const int tid = threadIdx.x;
    const int tx = tid & 31;
    const int ty = tid >> 5;
    const int base = blockIdx.x * 64;

    if (tid < 64) {
        int g = base + tid;
        if (g > N_NODES - 1) g = N_NODES - 1;
        sScale[tid] = g_rs_d[g];
    }
    __syncthreads();

    u64 acc2[8][2];
#pragma unroll
    for (int r = 0; r < 8; ++r) { acc2[r][0] = 0ull; acc2[r][1] = 0ull; }

    for (int kc = 0; kc < 4; ++kc) {
#pragma unroll
        for (int it = 0; it < 2; ++it) {
            int f = tid + it * 256;
            int row = f >> 3;
            int k4 = f & 7;
            int g = base + row;
            if (g > N_NODES - 1) g = N_NODES - 1;
            float4 v = *reinterpret_cast<const float4*>(
                g_agg + (size_t)g * FEATS + kc * 32 + k4 * 4);
            float sc = sScale[row];
            v.x *= sc; v.y *= sc; v.z *= sc; v.w *= sc;
            *reinterpret_cast<float4*>(&sA[row][k4 * 4]) = v;
        }
#pragma unroll
        for (int it = 0; it < 4; ++it) {
            int f = tid + it * 256;
            int k = f >> 5;
            int c4 = f & 31;
            float4 v = *reinterpret_cast<const float4*>(
                W + (size_t)(kc * 32 + k) * FEATS + c4 * 4);
            *reinterpret_cast<float4*>(&sB[k][c4 * 4]) = v;
        }
        __syncthreads();

#pragma unroll
        for (int kq = 0; kq < 8; ++kq) {
            u64 b01[4], b23[4];
#pragma unroll
            for (int j = 0; j < 4; ++j) {
                const u64* bp = reinterpret_cast<const u64*>(&sB[kq * 4 + j][tx * 4]);
                b01[j] = bp[0];
                b23[j] = bp[1];
            }
#pragma unroll
            for (int r = 0; r < 8; ++r) {
                float4 a = *reinterpret_cast<const float4*>(&sA[ty * 8 + r][kq * 4]);
                acc2[r][0] = fma_f32x2(splat_f32x2(a.x), b01[0], acc2[r][0]);
                acc2[r][1] = fma_f32x2(splat_f32x2(a.x), b23[0], acc2[r][1]);
                acc2[r][0] = fma_f32x2(splat_f32x2(a.y), b01[1], acc2[r][0]);
                acc2[r][1] = fma_f32x2(splat_f32x2(a.y), b23[1], acc2[r][1]);
                acc2[r][0] = fma_f32x2(splat_f32x2(a.z), b01[2], acc2[r][0]);
                acc2[r][1] = fma_f32x2(splat_f32x2(a.z), b23[2], acc2[r][1]);
                acc2[r][0] = fma_f32x2(splat_f32x2(a.w), b01[3], acc2[r][0]);
                acc2[r][1] = fma_f32x2(splat_f32x2(a.w), b23[3], acc2[r][1]);
            }
        }
        __syncthreads();
    }

    float4 bb = *reinterpret_cast<const float4*>(bias + tx * 4);
#pragma unroll
    for (int r = 0; r < 8; ++r) {
        int g = base + ty * 8 + r;
        if (g < N_NODES) {
            float a0, a1, a2, a3;
            unpack_f32x2(acc2[r][0], a0, a1);
            unpack_f32x2(acc2[r][1], a2, a3);
            float4 o;
            o.x = fmaxf(a0 + bb.x, 0.f);
            o.y = fmaxf(a1 + bb.y, 0.f);
            o.z = fmaxf(a2 + bb.z, 0.f);
            o.w = fmaxf(a3 + bb.w, 0.f);
            *reinterpret_cast<float4*>(out + (size_t)g * FEATS + tx * 4) = o;
        }
    }
}

// ---------------------------------------------------------------------------
extern "C" void kernel_launch(void* const* d_in, const int* in_sizes, int n_in,
                              void* d_out, int out_size) {
    const float* features = (const float*)d_in[0];
    const int*   src      = (const int*)d_in[1];
    const int*   dst      = (const int*)d_in[2];
    const float* weight   = (const float*)d_in[3];
    const float* bias     = (const float*)d_in[4];
    float* out = (float*)d_out;

    static void* p_deg = nullptr;
    static void* p_cur = nullptr;
    static void* p_off = nullptr;
    if (!p_deg) {
        cudaGetSymbolAddress(&p_deg, g_deg);
        cudaGetSymbolAddress(&p_cur, g_cur);
        cudaGetSymbolAddress(&p_off, g_off);
    }

    // Zero degree counters (single contiguous memset on the copy engine).
    cudaMemsetAsync(p_deg, 0, sizeof(int) * 2 * N_NODES);

    // Degrees.
    degree_kernel<<<((N_EDGES / 4) + 255) / 256, 256>>>(src, dst);

    // CSR offsets (scan1 + scan2 + fused scan3/rsqrt).
    scan1_kernel<<<NBLK, 1024>>>();
    scan2_kernel<<<1, 128>>>();
    scan3_rsqrt_kernel<<<(N_NODES + 255) / 256, 256>>>();

    // Cursors start at row offsets (device-to-device copy, capture-legal).
    cudaMemcpyAsync(p_cur, p_off, sizeof(int) * N_NODES,
                    cudaMemcpyDeviceToDevice);

    // Binning (atomic return value = absolute CSR slot).
    bin_kernel<<<((N_EDGES / 4) + 255) / 256, 256>>>(src, dst);

    // Register-accumulated aggregation (warp per dst node).
    aggregate_kernel<<<(N_NODES * 32 + 255) / 256, 256>>>(features);

    // GEMM + rs_in scale + bias + relu.
    gemm_kernel<<<(N_NODES + 63) / 64, 256>>>(weight, bias, out);
}